// round 13
// baseline (speedup 1.0000x reference)
#include <cuda_runtime.h>
#include <cuda_bf16.h>
#include <math.h>
#include <stdint.h>

#define SEQ 4096
#define DM  2048
#define NH  16
#define DQK 128

typedef __nv_bfloat16 bf16;

// ---------------- single 128 MiB heap, phase-overlaid (audited in R10) ------
__device__ __align__(1024) unsigned char g_heap[134217728];
#define QOFF 0u
#define KOFF 33554432u
#define ZOFF 67108864u
#define WH   100663296u
#define WL   109051904u
#define VTH  100663296u
#define VTL  117440512u
#define OTH  0u
#define OTL  8388608u

// ---------------- helpers ---------------------------------------------------
__device__ __forceinline__ void mma16816(float* c, const uint32_t* a, const uint32_t* b) {
    asm volatile(
        "mma.sync.aligned.m16n8k16.row.col.f32.bf16.bf16.f32 "
        "{%0,%1,%2,%3}, {%4,%5,%6,%7}, {%8,%9}, {%0,%1,%2,%3};"
        : "+f"(c[0]), "+f"(c[1]), "+f"(c[2]), "+f"(c[3])
        : "r"(a[0]), "r"(a[1]), "r"(a[2]), "r"(a[3]), "r"(b[0]), "r"(b[1]));
}
__device__ __forceinline__ void ldsm4(uint32_t* r, uint32_t a) {
    asm volatile("ldmatrix.sync.aligned.m8n8.x4.shared.b16 {%0,%1,%2,%3}, [%4];"
                 : "=r"(r[0]), "=r"(r[1]), "=r"(r[2]), "=r"(r[3]) : "r"(a));
}
__device__ __forceinline__ uint32_t smem_u32(const void* p) {
    uint32_t a;
    asm("{ .reg .u64 t; cvta.to.shared.u64 t, %1; cvt.u32.u64 %0, t; }"
        : "=r"(a) : "l"(p));
    return a;
}
#define CPA16(dst, src) \
    asm volatile("cp.async.cg.shared.global [%0], [%1], 16;" :: "r"(dst), "l"(src))
#define CPA_COMMIT() asm volatile("cp.async.commit_group;" ::: "memory")
#define CPA_WAIT_ALL() asm volatile("cp.async.wait_all;" ::: "memory")
#define CPA_WAIT1() asm volatile("cp.async.wait_group 1;" ::: "memory")

__device__ __forceinline__ uint32_t pack_split(float a, float b, uint32_t& lopk) {
    bf16 ha = __float2bfloat16(a), hb = __float2bfloat16(b);
    bf16 la = __float2bfloat16(a - __bfloat162float(ha));
    bf16 lb = __float2bfloat16(b - __bfloat162float(hb));
    lopk = (uint32_t)__bfloat16_as_ushort(la) |
           ((uint32_t)__bfloat16_as_ushort(lb) << 16);
    return (uint32_t)__bfloat16_as_ushort(ha) |
           ((uint32_t)__bfloat16_as_ushort(hb) << 16);
}

// ---------------------------------------------------------------------------
// GEMM v8: 64-row CTA, 256 threads, 8 warps (warp tile 64x16, wm=0),
// dynamic smem 61440 -> 2 CTAs/SM. 2-stage, wait_group 1 (R10-proven flow).
// C[64,128] = A[64,K=2048] @ (Bh+Bl)[128rows][K]^T.
// Stage (30720 B): Ah +0 (5120), Al +5120, Bh +10240 (10240), Bl +20480.
// Fragment/ldsm addressing = R8-proven mapping with wm = 0.
// ---------------------------------------------------------------------------
__device__ __forceinline__ void gemm_v8(
    const float* __restrict__ A, int lda,
    const bf16* __restrict__ Bh, const bf16* __restrict__ Bl, int ldb,
    float* __restrict__ C, int ldc, float scale)
{
    extern __shared__ __align__(16) unsigned char sm[];
    const uint32_t sb = smem_u32(sm);

    const int t = threadIdx.x, lane = t & 31, wid = t >> 5;
    const int wn = wid * 16;

    // A loader: 64 rows x 4 thr/row, 8 fp32 each
    const int arow = t >> 2, aseg = t & 3;
    const float* pA = A + (size_t)arow * lda + aseg * 8;
    const uint32_t asoff = arow * 80u + aseg * 16u;

    // B loader: hi/lo tile x 128 rows, 1 thr/row, 64 B/chunk
    const int bt = t >> 7, brow = t & 127;
    const char* pB = (const char*)((bt ? Bl : Bh) + (size_t)brow * ldb);
    const uint32_t bsoff = 10240u + bt * 10240u + brow * 80u;

    float acc[4][2][4];
#pragma unroll
    for (int i = 0; i < 4; i++)
#pragma unroll
        for (int j = 0; j < 2; j++)
#pragma unroll
            for (int r = 0; r < 4; r++) acc[i][j][r] = 0.0f;

    float a_f[8];
#define PREF_A(kc) do { \
        const float* ap_ = pA + (size_t)(kc) * 32; \
        float4 v0_ = *(const float4*)ap_; \
        float4 v1_ = *(const float4*)(ap_ + 4); \
        a_f[0] = v0_.x; a_f[1] = v0_.y; a_f[2] = v0_.z; a_f[3] = v0_.w; \
        a_f[4] = v1_.x; a_f[5] = v1_.y; a_f[6] = v1_.z; a_f[7] = v1_.w; \
    } while (0)
#define ISSUE_B(kc, st) do { \
        const char* src_ = pB + (size_t)(kc) * 64; \
        CPA16(sb + (st) + bsoff,      src_); \
        CPA16(sb + (st) + bsoff + 16, src_ + 16); \
        CPA16(sb + (st) + bsoff + 32, src_ + 32); \
        CPA16(sb + (st) + bsoff + 48, src_ + 48); \
        CPA_COMMIT(); \
    } while (0)

    PREF_A(0);
    ISSUE_B(0, 0u);

    for (int kc = 0; kc < 64; kc++) {
        const uint32_t st = (kc & 1) * 30720u;
        __syncthreads();   // prior compute done reading this stage

        // pack A chunk kc (held in a_f)
        {
            uint32_t hi[4], lo[4];
            hi[0] = pack_split(a_f[0], a_f[1], lo[0]);
            hi[1] = pack_split(a_f[2], a_f[3], lo[1]);
            hi[2] = pack_split(a_f[4], a_f[5], lo[2]);
            hi[3] = pack_split(a_f[6], a_f[7], lo[3]);
            *(uint4*)(sm + st + asoff)        = make_uint4(hi[0], hi[1], hi[2], hi[3]);
            *(uint4*)(sm + st + 5120 + asoff) = make_uint4(lo[0], lo[1], lo[2], lo[3]);
        }
        if (kc < 63) {
            ISSUE_B(kc + 1, st ^ 30720u);
            PREF_A(kc + 1);
            CPA_WAIT1();     // retire group kc (kc+1 stays in flight)
        } else {
            CPA_WAIT_ALL();
        }
        __syncthreads();

#pragma unroll
        for (int ks = 0; ks < 2; ks++) {
            uint32_t ah[4][4], al[4][4], bh4[4], bl4[4];
            const uint32_t abase = sb + st +
                ((lane & 7) + ((lane >> 3) & 1) * 8) * 80 + ks * 32 + (lane >> 4) * 16;
#pragma unroll
            for (int i = 0; i < 4; i++) {
                ldsm4(ah[i], abase + i * 1280);
                ldsm4(al[i], abase + 5120 + i * 1280);
            }
            const uint32_t bbase = sb + st + 10240 +
                (wn + (lane & 7) + ((lane >> 4) & 1) * 8) * 80 + ks * 32 + ((lane >> 3) & 1) * 16;
            ldsm4(bh4, bbase);
            ldsm4(bl4, bbase + 10240);
#pragma unroll
            for (int i = 0; i < 4; i++)
#pragma unroll
                for (int j = 0; j < 2; j++) {
                    mma16816(acc[i][j], ah[i], &bh4[j * 2]);
                    mma16816(acc[i][j], al[i], &bh4[j * 2]);
                    mma16816(acc[i][j], ah[i], &bl4[j * 2]);
                }
        }
    }
#undef PREF_A
#undef ISSUE_B

    const int g = lane >> 2, qq = lane & 3;
#pragma unroll
    for (int i = 0; i < 4; i++)
#pragma unroll
        for (int j = 0; j < 2; j++) {
            const int row = i * 16 + g;
            const int col = wn + j * 8 + qq * 2;
            float2 lo = make_float2(acc[i][j][0] * scale, acc[i][j][1] * scale);
            float2 hi = make_float2(acc[i][j][2] * scale, acc[i][j][3] * scale);
            *(float2*)(C + (size_t)row * ldc + col)       = lo;
            *(float2*)(C + (size_t)(row + 8) * ldc + col) = hi;
        }
}

__global__ void __launch_bounds__(256, 2) proj_v8(const float* __restrict__ x,
                                                 unsigned dstoff)
{
    const int h = blockIdx.y;
    const bf16* bh = (const bf16*)(g_heap + WH) + (size_t)h * 262144;
    const bf16* bl = (const bf16*)(g_heap + WL) + (size_t)h * 262144;
    float* C = (float*)(g_heap + dstoff) +
               (size_t)h * SEQ * DQK + (size_t)blockIdx.x * 64 * DQK;
    gemm_v8(x + (size_t)blockIdx.x * 64 * DM, DM, bh, bl, DM, C, DQK, 1.0f);
}

__global__ void __launch_bounds__(256, 2) outproj_v8(float* __restrict__ out)
{
    const float* z = (const float*)(g_heap + ZOFF);
    const bf16* bh = (const bf16*)(g_heap + OTH) + (size_t)blockIdx.y * 128 * 2048;
    const bf16* bl = (const bf16*)(g_heap + OTL) + (size_t)blockIdx.y * 128 * 2048;
    gemm_v8(z + (size_t)blockIdx.x * 64 * 2048, 2048, bh, bl, 2048,
            out + (size_t)blockIdx.x * 64 * DM + blockIdx.y * 128,
            DM, 4.8828125e-4f);
}

// ---------------------------------------------------------------------------
// prep kernels (R10-verbatim)
// ---------------------------------------------------------------------------
__global__ void __launch_bounds__(256) splitwT(const float* __restrict__ w)
{
    __shared__ float tile[32][33];
    const int h = blockIdx.z;
    const float* src = w + (size_t)h * 262144;
    bf16* oh = (bf16*)(g_heap + WH) + (size_t)h * 262144;
    bf16* ol = (bf16*)(g_heap + WL) + (size_t)h * 262144;
    const int tx = threadIdx.x, ty = threadIdx.y;
    const int k0 = blockIdx.x * 32, n0 = blockIdx.y * 32;
#pragma unroll
    for (int i = 0; i < 4; i++)
        tile[ty + 8 * i][tx] = src[(size_t)(k0 + ty + 8 * i) * 128 + n0 + tx];
    __syncthreads();
#pragma unroll
    for (int i = 0; i < 4; i++) {
        float v = tile[tx][ty + 8 * i];
        bf16 hh = __float2bfloat16(v);
        oh[(size_t)(n0 + ty + 8 * i) * 2048 + k0 + tx] = hh;
        ol[(size_t)(n0 + ty + 8 * i) * 2048 + k0 + tx] =
            __float2bfloat16(v - __bfloat162float(hh));
    }
}

__global__ void __launch_bounds__(256) osplitT(const float* __restrict__ o)
{
    __shared__ float tile[32][33];
    bf16* oh = (bf16*)(g_heap + OTH);
    bf16* ol = (bf16*)(g_heap + OTL);
    const int tx = threadIdx.x, ty = threadIdx.y;
    const int a0 = blockIdx.x * 32, d0 = blockIdx.y * 32;
#pragma unroll
    for (int i = 0; i < 4; i++)
        tile[ty + 8 * i][tx] = o[(size_t)(a0 + ty + 8 * i) * 2048 + d0 + tx];
    __syncthreads();
#pragma unroll
    for (int i = 0; i < 4; i++) {
        float v = tile[tx][ty + 8 * i];
        bf16 hh = __float2bfloat16(v);
        oh[(size_t)(d0 + ty + 8 * i) * 2048 + a0 + tx] = hh;
        ol[(size_t)(d0 + ty + 8 * i) * 2048 + a0 + tx] =
            __float2bfloat16(v - __bfloat162float(hh));
    }
}

__global__ void __launch_bounds__(256) rope_pack(const float* __restrict__ theta)
{
    const float tf = theta[0];
    const int s = blockIdx.x * 4 + (threadIdx.x >> 6);
    const int j = threadIdx.x & 63;
    const int h = blockIdx.y;
    char* base = (char*)g_heap + (blockIdx.z ? KOFF : QOFF) +
                 ((size_t)(h * 4096 + s)) * 512;
    float* rowp = (float*)base;

    const float x1 = rowp[j];
    const float x2 = rowp[j + 64];
    const float rate = tf * (-(float)j * 0.015625f);
    const float rot  = __fmul_rn((float)s, rate);
    float sv, cv;
    sincosf(rot, &sv, &cv);
    const float y1 = (cv * x1 - sv * x2) / 3.36358566101485845f;
    const float y2 = (sv * x1 + cv * x2) / 3.36358566101485845f;

    __syncthreads();

    bf16* hp = (bf16*)base;
    bf16 h1 = __float2bfloat16(y1);
    bf16 h2 = __float2bfloat16(y2);
    hp[j]            = h1;
    hp[j + 64]       = h2;
    hp[128 + j]      = __float2bfloat16(y1 - __bfloat162float(h1));
    hp[128 + j + 64] = __float2bfloat16(y2 - __bfloat162float(h2));
}

__global__ void __launch_bounds__(256) tspv()
{
    __shared__ float tile[32][33];
    const int h = blockIdx.z;
    const float* pv = (const float*)(g_heap + ZOFF) + (size_t)h * 4096 * 128;
    bf16* vh = (bf16*)(g_heap + VTH) + (size_t)h * 128 * 4096;
    bf16* vl = (bf16*)(g_heap + VTL) + (size_t)h * 128 * 4096;
    const int tx = threadIdx.x, ty = threadIdx.y;
    const int s0 = blockIdx.x * 32, v0 = blockIdx.y * 32;
#pragma unroll
    for (int i = 0; i < 4; i++)
        tile[ty + 8 * i][tx] = pv[(size_t)(s0 + ty + 8 * i) * 128 + v0 + tx];
    __syncthreads();
#pragma unroll
    for (int i = 0; i < 4; i++) {
        float v = tile[tx][ty + 8 * i];
        bf16 hh = __float2bfloat16(v);
        vh[(size_t)(v0 + ty + 8 * i) * 4096 + s0 + tx] = hh;
        vl[(size_t)(v0 + ty + 8 * i) * 4096 + s0 + tx] =
            __float2bfloat16(v - __bfloat162float(hh));
    }
}

// ---------------------------------------------------------------------------
// Flash attention (R11/R12-proven: Q fragments hoisted to registers)
// ---------------------------------------------------------------------------
#define AQH 0u
#define AQL 34816u
#define ABUF 69632u
#define BUFSZ 71680u
#define BKH 0u
#define BKL 17408u
#define BVH 34816u
#define BVL 53248u

__global__ void __launch_bounds__(256) attn_hmma()
{
    extern __shared__ char smem[];
    const uint32_t sb = smem_u32(smem);
    const int t = threadIdx.x, lane = t & 31, wid = t >> 5;
    const int g = lane >> 2, qq = lane & 3;
    const int bx = blockIdx.x;
    const int qt = 31 - (bx >> 4);
    const int h  = bx & 15;
    const int r0 = qt * 128;
    const int jmax = 2 * qt + 1;

    const char* qbase = (const char*)g_heap + QOFF + ((size_t)(h * 4096 + r0)) * 512;
    const char* kbase = (const char*)g_heap + KOFF + ((size_t)h * 4096) * 512;

    {
        const char* src = qbase + (size_t)(t & 127) * 512 + (t >> 7) * 256;
        const uint32_t dst = sb + ((t >> 7) ? AQL : AQH) + (t & 127) * 272;
#pragma unroll
        for (int u = 0; u < 16; u++) CPA16(dst + u * 16, src + u * 16);
    }
    const int krow = t & 63, kseg = (t >> 6) & 1, kha = t >> 7;
    const int vrow = t & 127, vha = t >> 7;
    const char* vsrc0 = (const char*)g_heap + (vha ? VTL : VTH) +
                        ((size_t)h * 128 + vrow) * 8192;
    {
        const char* ksrc = kbase + (size_t)krow * 512 + kha * 256 + kseg * 128;
        const uint32_t kdst = sb + ABUF + (kha ? BKL : BKH) + krow * 272 + kseg * 128;
#pragma unroll
        for (int u = 0; u < 8; u++) CPA16(kdst + u * 16, ksrc + u * 16);
        const uint32_t vdst = sb + ABUF + (vha ? BVL : BVH) + vrow * 144;
#pragma unroll
        for (int u = 0; u < 8; u++) CPA16(vdst + u * 16, vsrc0 + u * 16);
    }
    CPA_COMMIT();

    CPA_WAIT_ALL();
    __syncthreads();
    uint32_t qfh[8][4], qfl[8][4];
#pragma unroll
    for (int ks = 0; ks < 8; ks++) {
        const uint32_t qa = sb + AQH +
            (wid * 16 + (lane & 7) + ((lane >> 3) & 1) * 8) * 272 +
            ks * 32 + (lane >> 4) * 16;
        ldsm4(qfh[ks], qa);
        ldsm4(qfl[ks], qa + 34816);
    }

    float zacc[16][4];
#pragma unroll
    for (int n = 0; n < 16; n++)
#pragma unroll
        for (int r = 0; r < 4; r++) zacc[n][r] = 0.0f;
    float m0 = -3e38f, m1 = -3e38f, l0 = 0.0f, l1 = 0.0f;

    for (int j = 0; j <= jmax; j++) {
        const int b = j & 1;
        const uint32_t sbuf = sb + ABUF + b * BUFSZ;
        CPA_WAIT_ALL();
        __syncthreads();

        if (j < jmax) {
            const int col1 = (j + 1) * 64;
            const uint32_t ob = sb + ABUF + (b ^ 1) * BUFSZ;
            const char* ksrc = kbase + (size_t)(col1 + krow) * 512 + kha * 256 + kseg * 128;
            const uint32_t kdst = ob + (kha ? BKL : BKH) + krow * 272 + kseg * 128;
#pragma unroll
            for (int u = 0; u < 8; u++) CPA16(kdst + u * 16, ksrc + u * 16);
            const char* vsrc = vsrc0 + col1 * 2;
            const uint32_t vdst = ob + (vha ? BVL : BVH) + vrow * 144;
#pragma unroll
            for (int u = 0; u < 8; u++) CPA16(vdst + u * 16, vsrc + u * 16);
            CPA_COMMIT();
        }

        float sacc[8][4];
#pragma unroll
        for (int n = 0; n < 8; n++)
#pragma unroll
            for (int r = 0; r < 4; r++) sacc[n][r] = 0.0f;

#pragma unroll
        for (int ks = 0; ks < 8; ks++) {
#pragma unroll
            for (int n2 = 0; n2 < 4; n2++) {
                uint32_t kh[4], kl[4];
                const uint32_t ka = sbuf + BKH +
                    (n2 * 16 + (lane & 7) + ((lane >> 4) & 1) * 8) * 272 +
                    ks * 32 + ((lane >> 3) & 1) * 16;
                ldsm4(kh, ka);
                ldsm4(kl, ka + 17408);
#pragma unroll
                for (int bb = 0; bb < 2; bb++) {
                    const int n = 2 * n2 + bb;
                    mma16816(sacc[n], qfh[ks], &kh[bb * 2]);
                    mma16816(sacc[n], qfl[ks], &kh[bb * 2]);
                    mma16816(sacc[n], qfh[ks], &kl[bb * 2]);
                }
            }
        }

        if (j >= 2 * qt) {
            const int rowlo = r0 + wid * 16 + g;
            const int colb  = j * 64 + qq * 2;
#pragma unroll
            for (int n = 0; n < 8; n++) {
                const int c0 = colb + n * 8, c1 = c0 + 1;
                if (c0 > rowlo)     sacc[n][0] = -1e30f;
                if (c1 > rowlo)     sacc[n][1] = -1e30f;
                if (c0 > rowlo + 8) sacc[n][2] = -1e30f;
                if (c1 > rowlo + 8) sacc[n][3] = -1e30f;
            }
        }

        float rm0 = -3e38f, rm1 = -3e38f;
#pragma unroll
        for (int n = 0; n < 8; n++) {
            rm0 = fmaxf(rm0, fmaxf(sacc[n][0], sacc[n][1]));
            rm1 = fmaxf(rm1, fmaxf(sacc[n][2], sacc[n][3]));
        }
        rm0 = fmaxf(rm0, __shfl_xor_sync(0xffffffffu, rm0, 1));
        rm0 = fmaxf(rm0, __shfl_xor_sync(0xffffffffu, rm0, 2));
        rm1 = fmaxf(rm1, __shfl_xor_sync(0xffffffffu, rm1, 1));
        rm1 = fmaxf(rm1, __shfl_xor_sync(0xffffffffu, rm1, 2));
        const float mn0 = fmaxf(m0, rm0), mn1 = fmaxf(m1, rm1);
        const float al0 = __expf(m0 - mn0), al1 = __expf(m1 - mn1);
        m0 = mn0; m1 = mn1;

        float rs0 = 0.0f, rs1 = 0.0f;
#pragma unroll
        for (int n = 0; n < 8; n++) {
            sacc[n][0] = __expf(sacc[n][0] - mn0);
            sacc[n][1] = __expf(sacc[n][1] - mn0);
            sacc[n][2] = __expf(sacc[n][2] - mn1);
            sacc[n][3] = __expf(sacc[n][3] - mn1);
            rs0 += sacc[n][0] + sacc[n][1];
            rs1 += sacc[n][2] + sacc[n][3];
        }
        rs0 += __shfl_xor_sync(0xffffffffu, rs0, 1);
        rs0 += __shfl_xor_sync(0xffffffffu, rs0, 2);
        rs1 += __shfl_xor_sync(0xffffffffu, rs1, 1);
        rs1 += __shfl_xor_sync(0xffffffffu, rs1, 2);
        l0 = l0 * al0 + rs0;
        l1 = l1 * al1 + rs1;

#pragma unroll
        for (int n = 0; n < 16; n++) {
            zacc[n][0] *= al0; zacc[n][1] *= al0;
            zacc[n][2] *= al1; zacc[n][3] *= al1;
        }

        uint32_t pa_h[4][4], pa_l[4][4];
#pragma unroll
        for (int kt = 0; kt < 4; kt++) {
            pa_h[kt][0] = pack_split(sacc[2*kt][0],   sacc[2*kt][1],   pa_l[kt][0]);
            pa_h[kt][1] = pack_split(sacc[2*kt][2],   sacc[2*kt][3],   pa_l[kt][1]);
            pa_h[kt][2] = pack_split(sacc[2*kt+1][0], sacc[2*kt+1][1], pa_l[kt][2]);
            pa_h[kt][3] = pack_split(sacc[2*kt+1][2], sacc[2*kt+1][3], pa_l[kt][3]);
        }

#pragma unroll
        for (int kt = 0; kt < 4; kt++) {
#pragma unroll
            for (int n2 = 0; n2 < 8; n2++) {
                uint32_t vh[4], vl[4];
                const uint32_t va = sbuf + BVH +
                    (n2 * 16 + (lane & 7) + ((lane >> 4) & 1) * 8) * 144 +
                    kt * 32 + ((lane >> 3) & 1) * 16;
                ldsm4(vh, va);
                ldsm4(vl, va + 18432);
#pragma unroll
                for (int bb = 0; bb < 2; bb++) {
                    const int n = 2 * n2 + bb;
                    mma16816(zacc[n], pa_h[kt], &vh[bb * 2]);
                    mma16816(zacc[n], pa_l[kt], &vh[bb * 2]);
                    mma16816(zacc[n], pa_h[kt], &vl[bb * 2]);
                }
            }
        }
        __syncthreads();
    }

    const float i0 = 1.0f / l0, i1 = 1.0f / l1;
    float* zp = (float*)(g_heap + ZOFF);
    const int rowlo = r0 + wid * 16 + g;
#pragma unroll
    for (int n = 0; n < 16; n++) {
        const int col = h * 128 + n * 8 + qq * 2;
        *(float2*)(zp + (size_t)rowlo * 2048 + col) =
            make_float2(zacc[n][0] * i0, zacc[n][1] * i0);
        *(float2*)(zp + (size_t)(rowlo + 8) * 2048 + col) =
            make_float2(zacc[n][2] * i1, zacc[n][3] * i1);
    }
}

// ---------------------------------------------------------------------------
extern "C" void kernel_launch(void* const* d_in, const int* in_sizes, int n_in,
                              void* d_out, int out_size)
{
    const float* x     = (const float*)d_in[0];
    const float* q     = (const float*)d_in[1];
    const float* k     = (const float*)d_in[2];
    const float* v     = (const float*)d_in[3];
    const float* o     = (const float*)d_in[4];
    const float* theta = (const float*)d_in[5];
    float* out = (float*)d_out;

    cudaFuncSetAttribute(attn_hmma,
                         cudaFuncAttributeMaxDynamicSharedMemorySize, 212992);
    cudaFuncSetAttribute(proj_v8,
                         cudaFuncAttributeMaxDynamicSharedMemorySize, 61440);
    cudaFuncSetAttribute(outproj_v8,
                         cudaFuncAttributeMaxDynamicSharedMemorySize, 61440);

    splitwT<<<dim3(64, 4, 16), dim3(32, 8)>>>(q);
    proj_v8<<<dim3(64, 16), 256, 61440>>>(x, QOFF);
    splitwT<<<dim3(64, 4, 16), dim3(32, 8)>>>(k);
    proj_v8<<<dim3(64, 16), 256, 61440>>>(x, KOFF);
    splitwT<<<dim3(64, 4, 16), dim3(32, 8)>>>(v);
    proj_v8<<<dim3(64, 16), 256, 61440>>>(x, ZOFF);
    rope_pack<<<dim3(1024, 16, 2), 256>>>(theta);
    tspv<<<dim3(128, 4, 16), dim3(32, 8)>>>();
    attn_hmma<<<512, 256, 212992>>>();
    osplitT<<<dim3(64, 64), dim3(32, 8)>>>(o);
    outproj_v8<<<dim3(64, 16), 256, 61440>>>(out);
}

// round 14
// speedup vs baseline: 1.0302x; 1.0302x over previous
#include <cuda_runtime.h>
#include <cuda_bf16.h>
#include <math.h>
#include <stdint.h>

#define SEQ 4096
#define DM  2048
#define NH  16
#define DQK 128

typedef __nv_bfloat16 bf16;

// ---------------- single 128 MiB heap, phase-overlaid (audited in R10) ------
__device__ __align__(1024) unsigned char g_heap[134217728];
#define QOFF 0u
#define KOFF 33554432u
#define ZOFF 67108864u
#define WH   100663296u
#define WL   109051904u
#define VTH  100663296u
#define VTL  117440512u
#define OTH  0u
#define OTL  8388608u

// ---------------- helpers ---------------------------------------------------
__device__ __forceinline__ void mma16816(float* c, const uint32_t* a, const uint32_t* b) {
    asm volatile(
        "mma.sync.aligned.m16n8k16.row.col.f32.bf16.bf16.f32 "
        "{%0,%1,%2,%3}, {%4,%5,%6,%7}, {%8,%9}, {%0,%1,%2,%3};"
        : "+f"(c[0]), "+f"(c[1]), "+f"(c[2]), "+f"(c[3])
        : "r"(a[0]), "r"(a[1]), "r"(a[2]), "r"(a[3]), "r"(b[0]), "r"(b[1]));
}
__device__ __forceinline__ void ldsm4(uint32_t* r, uint32_t a) {
    asm volatile("ldmatrix.sync.aligned.m8n8.x4.shared.b16 {%0,%1,%2,%3}, [%4];"
                 : "=r"(r[0]), "=r"(r[1]), "=r"(r[2]), "=r"(r[3]) : "r"(a));
}
__device__ __forceinline__ uint32_t smem_u32(const void* p) {
    uint32_t a;
    asm("{ .reg .u64 t; cvta.to.shared.u64 t, %1; cvt.u32.u64 %0, t; }"
        : "=r"(a) : "l"(p));
    return a;
}
#define CPA16(dst, src) \
    asm volatile("cp.async.cg.shared.global [%0], [%1], 16;" :: "r"(dst), "l"(src))
#define CPA_COMMIT() asm volatile("cp.async.commit_group;" ::: "memory")
#define CPA_WAIT_ALL() asm volatile("cp.async.wait_all;" ::: "memory")
#define CPA_WAIT1() asm volatile("cp.async.wait_group 1;" ::: "memory")

__device__ __forceinline__ uint32_t pack_split(float a, float b, uint32_t& lopk) {
    bf16 ha = __float2bfloat16(a), hb = __float2bfloat16(b);
    bf16 la = __float2bfloat16(a - __bfloat162float(ha));
    bf16 lb = __float2bfloat16(b - __bfloat162float(hb));
    lopk = (uint32_t)__bfloat16_as_ushort(la) |
           ((uint32_t)__bfloat16_as_ushort(lb) << 16);
    return (uint32_t)__bfloat16_as_ushort(ha) |
           ((uint32_t)__bfloat16_as_ushort(hb) << 16);
}

// ---------------------------------------------------------------------------
// GEMM v9 = v7 (R12, proven) with PASS-MAJOR MMA ordering in the inner loop.
// 3-stage pipeline, one sync per chunk, wait_group 1.
// C[128,128] = A[128,K=2048] @ (Bh+Bl)[128rows][K]^T. 512 thr, 16 warps.
// Stage (40960 B): Ah +0, Al +10240, Bh +20480, Bl +30720 (80B row pitch).
// ---------------------------------------------------------------------------
__device__ __forceinline__ void gemm_v9(
    const float* __restrict__ A, int lda,
    const bf16* __restrict__ Bh, const bf16* __restrict__ Bl, int ldb,
    float* __restrict__ C, int ldc, float scale)
{
    __shared__ __align__(16) unsigned char sm[122880];
    const uint32_t sb = smem_u32(sm);

    const int t = threadIdx.x, lane = t & 31, wid = t >> 5;
    const int wm = (wid >> 3) * 64, wn = (wid & 7) * 16;

    const int arow = t >> 2, aseg = t & 3;
    const float* pA = A + (size_t)arow * lda + aseg * 8;
    const uint32_t asoff = arow * 80u + aseg * 16u;

    const int bt = t >> 8, brow = (t >> 1) & 127, bseg = t & 1;
    const char* pB = (const char*)((bt ? Bl : Bh) + (size_t)brow * ldb) + bseg * 32;
    const uint32_t bsoff = 20480u + bt * 10240u + brow * 80u + bseg * 32u;

    float acc[4][2][4];
#pragma unroll
    for (int i = 0; i < 4; i++)
#pragma unroll
        for (int j = 0; j < 2; j++)
#pragma unroll
            for (int r = 0; r < 4; r++) acc[i][j][r] = 0.0f;

    float a_f[8];
#define PREF_A(kc) do { \
        const float* ap_ = pA + (size_t)(kc) * 32; \
        float4 v0_ = *(const float4*)ap_; \
        float4 v1_ = *(const float4*)(ap_ + 4); \
        a_f[0] = v0_.x; a_f[1] = v0_.y; a_f[2] = v0_.z; a_f[3] = v0_.w; \
        a_f[4] = v1_.x; a_f[5] = v1_.y; a_f[6] = v1_.z; a_f[7] = v1_.w; \
    } while (0)
#define PACK_A(st) do { \
        uint32_t hi_[4], lo_[4]; \
        hi_[0] = pack_split(a_f[0], a_f[1], lo_[0]); \
        hi_[1] = pack_split(a_f[2], a_f[3], lo_[1]); \
        hi_[2] = pack_split(a_f[4], a_f[5], lo_[2]); \
        hi_[3] = pack_split(a_f[6], a_f[7], lo_[3]); \
        *(uint4*)(sm + (st) + asoff)         = make_uint4(hi_[0], hi_[1], hi_[2], hi_[3]); \
        *(uint4*)(sm + (st) + 10240 + asoff) = make_uint4(lo_[0], lo_[1], lo_[2], lo_[3]); \
    } while (0)
#define ISSUE_B(kc, st) do { \
        const char* src_ = pB + (size_t)(kc) * 64; \
        CPA16(sb + (st) + bsoff, src_); \
        CPA16(sb + (st) + bsoff + 16, src_ + 16); \
        CPA_COMMIT(); \
    } while (0)

    PREF_A(0); PACK_A(0u);      ISSUE_B(0, 0u);
    PREF_A(1); PACK_A(40960u);  ISSUE_B(1, 40960u);
    PREF_A(2);

    uint32_t cur = 0u, fill = 81920u;
    for (int kc = 0; kc < 64; kc++) {
        if (kc < 63) CPA_WAIT1();
        else         CPA_WAIT_ALL();
        __syncthreads();

        if (kc + 2 < 64) {
            PACK_A(fill);
            ISSUE_B(kc + 2, fill);
            if (kc + 3 < 64) PREF_A(kc + 3);
        }

#pragma unroll
        for (int ks = 0; ks < 2; ks++) {
            uint32_t ah[4][4], al[4][4], bh4[4], bl4[4];
            const uint32_t abase = sb + cur +
                (wm + (lane & 7) + ((lane >> 3) & 1) * 8) * 80 + ks * 32 + (lane >> 4) * 16;
#pragma unroll
            for (int i = 0; i < 4; i++) {
                ldsm4(ah[i], abase + i * 1280);
                ldsm4(al[i], abase + 10240 + i * 1280);
            }
            const uint32_t bbase = sb + cur + 20480 +
                (wn + (lane & 7) + ((lane >> 4) & 1) * 8) * 80 + ks * 32 + ((lane >> 3) & 1) * 16;
            ldsm4(bh4, bbase);
            ldsm4(bl4, bbase + 10240);
            // PASS-MAJOR: adjacent MMAs hit different accumulators
#pragma unroll
            for (int i = 0; i < 4; i++)
#pragma unroll
                for (int j = 0; j < 2; j++)
                    mma16816(acc[i][j], ah[i], &bh4[j * 2]);
#pragma unroll
            for (int i = 0; i < 4; i++)
#pragma unroll
                for (int j = 0; j < 2; j++)
                    mma16816(acc[i][j], al[i], &bh4[j * 2]);
#pragma unroll
            for (int i = 0; i < 4; i++)
#pragma unroll
                for (int j = 0; j < 2; j++)
                    mma16816(acc[i][j], ah[i], &bl4[j * 2]);
        }

        cur  = (cur  == 81920u) ? 0u : cur  + 40960u;
        fill = (fill == 81920u) ? 0u : fill + 40960u;
    }
#undef PREF_A
#undef PACK_A
#undef ISSUE_B

    const int g = lane >> 2, qq = lane & 3;
#pragma unroll
    for (int i = 0; i < 4; i++)
#pragma unroll
        for (int j = 0; j < 2; j++) {
            const int row = wm + i * 16 + g;
            const int col = wn + j * 8 + qq * 2;
            float2 lo = make_float2(acc[i][j][0] * scale, acc[i][j][1] * scale);
            float2 hi = make_float2(acc[i][j][2] * scale, acc[i][j][3] * scale);
            *(float2*)(C + (size_t)row * ldc + col)       = lo;
            *(float2*)(C + (size_t)(row + 8) * ldc + col) = hi;
        }
}

__global__ void __launch_bounds__(512) proj_v9(const float* __restrict__ x,
                                              unsigned dstoff)
{
    const int h = blockIdx.y;
    const bf16* bh = (const bf16*)(g_heap + WH) + (size_t)h * 262144;
    const bf16* bl = (const bf16*)(g_heap + WL) + (size_t)h * 262144;
    float* C = (float*)(g_heap + dstoff) +
               (size_t)h * SEQ * DQK + (size_t)blockIdx.x * 128 * DQK;
    gemm_v9(x + (size_t)blockIdx.x * 128 * DM, DM, bh, bl, DM, C, DQK, 1.0f);
}

__global__ void __launch_bounds__(512) outproj_v9(float* __restrict__ out)
{
    const float* z = (const float*)(g_heap + ZOFF);
    const bf16* bh = (const bf16*)(g_heap + OTH) + (size_t)blockIdx.y * 128 * 2048;
    const bf16* bl = (const bf16*)(g_heap + OTL) + (size_t)blockIdx.y * 128 * 2048;
    gemm_v9(z + (size_t)blockIdx.x * 128 * 2048, 2048, bh, bl, 2048,
            out + (size_t)blockIdx.x * 128 * DM + blockIdx.y * 128,
            DM, 4.8828125e-4f);
}

// ---------------------------------------------------------------------------
// prep kernels (R10-verbatim)
// ---------------------------------------------------------------------------
__global__ void __launch_bounds__(256) splitwT(const float* __restrict__ w)
{
    __shared__ float tile[32][33];
    const int h = blockIdx.z;
    const float* src = w + (size_t)h * 262144;
    bf16* oh = (bf16*)(g_heap + WH) + (size_t)h * 262144;
    bf16* ol = (bf16*)(g_heap + WL) + (size_t)h * 262144;
    const int tx = threadIdx.x, ty = threadIdx.y;
    const int k0 = blockIdx.x * 32, n0 = blockIdx.y * 32;
#pragma unroll
    for (int i = 0; i < 4; i++)
        tile[ty + 8 * i][tx] = src[(size_t)(k0 + ty + 8 * i) * 128 + n0 + tx];
    __syncthreads();
#pragma unroll
    for (int i = 0; i < 4; i++) {
        float v = tile[tx][ty + 8 * i];
        bf16 hh = __float2bfloat16(v);
        oh[(size_t)(n0 + ty + 8 * i) * 2048 + k0 + tx] = hh;
        ol[(size_t)(n0 + ty + 8 * i) * 2048 + k0 + tx] =
            __float2bfloat16(v - __bfloat162float(hh));
    }
}

__global__ void __launch_bounds__(256) osplitT(const float* __restrict__ o)
{
    __shared__ float tile[32][33];
    bf16* oh = (bf16*)(g_heap + OTH);
    bf16* ol = (bf16*)(g_heap + OTL);
    const int tx = threadIdx.x, ty = threadIdx.y;
    const int a0 = blockIdx.x * 32, d0 = blockIdx.y * 32;
#pragma unroll
    for (int i = 0; i < 4; i++)
        tile[ty + 8 * i][tx] = o[(size_t)(a0 + ty + 8 * i) * 2048 + d0 + tx];
    __syncthreads();
#pragma unroll
    for (int i = 0; i < 4; i++) {
        float v = tile[tx][ty + 8 * i];
        bf16 hh = __float2bfloat16(v);
        oh[(size_t)(d0 + ty + 8 * i) * 2048 + a0 + tx] = hh;
        ol[(size_t)(d0 + ty + 8 * i) * 2048 + a0 + tx] =
            __float2bfloat16(v - __bfloat162float(hh));
    }
}

__global__ void __launch_bounds__(256) rope_pack(const float* __restrict__ theta)
{
    const float tf = theta[0];
    const int s = blockIdx.x * 4 + (threadIdx.x >> 6);
    const int j = threadIdx.x & 63;
    const int h = blockIdx.y;
    char* base = (char*)g_heap + (blockIdx.z ? KOFF : QOFF) +
                 ((size_t)(h * 4096 + s)) * 512;
    float* rowp = (float*)base;

    const float x1 = rowp[j];
    const float x2 = rowp[j + 64];
    const float rate = tf * (-(float)j * 0.015625f);
    const float rot  = __fmul_rn((float)s, rate);
    float sv, cv;
    sincosf(rot, &sv, &cv);
    const float y1 = (cv * x1 - sv * x2) / 3.36358566101485845f;
    const float y2 = (sv * x1 + cv * x2) / 3.36358566101485845f;

    __syncthreads();

    bf16* hp = (bf16*)base;
    bf16 h1 = __float2bfloat16(y1);
    bf16 h2 = __float2bfloat16(y2);
    hp[j]            = h1;
    hp[j + 64]       = h2;
    hp[128 + j]      = __float2bfloat16(y1 - __bfloat162float(h1));
    hp[128 + j + 64] = __float2bfloat16(y2 - __bfloat162float(h2));
}

__global__ void __launch_bounds__(256) tspv()
{
    __shared__ float tile[32][33];
    const int h = blockIdx.z;
    const float* pv = (const float*)(g_heap + ZOFF) + (size_t)h * 4096 * 128;
    bf16* vh = (bf16*)(g_heap + VTH) + (size_t)h * 128 * 4096;
    bf16* vl = (bf16*)(g_heap + VTL) + (size_t)h * 128 * 4096;
    const int tx = threadIdx.x, ty = threadIdx.y;
    const int s0 = blockIdx.x * 32, v0 = blockIdx.y * 32;
#pragma unroll
    for (int i = 0; i < 4; i++)
        tile[ty + 8 * i][tx] = pv[(size_t)(s0 + ty + 8 * i) * 128 + v0 + tx];
    __syncthreads();
#pragma unroll
    for (int i = 0; i < 4; i++) {
        float v = tile[tx][ty + 8 * i];
        bf16 hh = __float2bfloat16(v);
        vh[(size_t)(v0 + ty + 8 * i) * 4096 + s0 + tx] = hh;
        vl[(size_t)(v0 + ty + 8 * i) * 4096 + s0 + tx] =
            __float2bfloat16(v - __bfloat162float(hh));
    }
}

// ---------------------------------------------------------------------------
// Flash attention: R12 core with pass-major MMA ordering in QK and PV.
// ---------------------------------------------------------------------------
#define AQH 0u
#define AQL 34816u
#define ABUF 69632u
#define BUFSZ 71680u
#define BKH 0u
#define BKL 17408u
#define BVH 34816u
#define BVL 53248u

__global__ void __launch_bounds__(256) attn_hmma()
{
    extern __shared__ char smem[];
    const uint32_t sb = smem_u32(smem);
    const int t = threadIdx.x, lane = t & 31, wid = t >> 5;
    const int g = lane >> 2, qq = lane & 3;
    const int bx = blockIdx.x;
    const int qt = 31 - (bx >> 4);
    const int h  = bx & 15;
    const int r0 = qt * 128;
    const int jmax = 2 * qt + 1;

    const char* qbase = (const char*)g_heap + QOFF + ((size_t)(h * 4096 + r0)) * 512;
    const char* kbase = (const char*)g_heap + KOFF + ((size_t)h * 4096) * 512;

    {
        const char* src = qbase + (size_t)(t & 127) * 512 + (t >> 7) * 256;
        const uint32_t dst = sb + ((t >> 7) ? AQL : AQH) + (t & 127) * 272;
#pragma unroll
        for (int u = 0; u < 16; u++) CPA16(dst + u * 16, src + u * 16);
    }
    const int krow = t & 63, kseg = (t >> 6) & 1, kha = t >> 7;
    const int vrow = t & 127, vha = t >> 7;
    const char* vsrc0 = (const char*)g_heap + (vha ? VTL : VTH) +
                        ((size_t)h * 128 + vrow) * 8192;
    {
        const char* ksrc = kbase + (size_t)krow * 512 + kha * 256 + kseg * 128;
        const uint32_t kdst = sb + ABUF + (kha ? BKL : BKH) + krow * 272 + kseg * 128;
#pragma unroll
        for (int u = 0; u < 8; u++) CPA16(kdst + u * 16, ksrc + u * 16);
        const uint32_t vdst = sb + ABUF + (vha ? BVL : BVH) + vrow * 144;
#pragma unroll
        for (int u = 0; u < 8; u++) CPA16(vdst + u * 16, vsrc0 + u * 16);
    }
    CPA_COMMIT();

    CPA_WAIT_ALL();
    __syncthreads();
    uint32_t qfh[8][4], qfl[8][4];
#pragma unroll
    for (int ks = 0; ks < 8; ks++) {
        const uint32_t qa = sb + AQH +
            (wid * 16 + (lane & 7) + ((lane >> 3) & 1) * 8) * 272 +
            ks * 32 + (lane >> 4) * 16;
        ldsm4(qfh[ks], qa);
        ldsm4(qfl[ks], qa + 34816);
    }

    float zacc[16][4];
#pragma unroll
    for (int n = 0; n < 16; n++)
#pragma unroll
        for (int r = 0; r < 4; r++) zacc[n][r] = 0.0f;
    float m0 = -3e38f, m1 = -3e38f, l0 = 0.0f, l1 = 0.0f;

    for (int j = 0; j <= jmax; j++) {
        const int b = j & 1;
        const uint32_t sbuf = sb + ABUF + b * BUFSZ;
        CPA_WAIT_ALL();
        __syncthreads();

        if (j < jmax) {
            const int col1 = (j + 1) * 64;
            const uint32_t ob = sb + ABUF + (b ^ 1) * BUFSZ;
            const char* ksrc = kbase + (size_t)(col1 + krow) * 512 + kha * 256 + kseg * 128;
            const uint32_t kdst = ob + (kha ? BKL : BKH) + krow * 272 + kseg * 128;
#pragma unroll
            for (int u = 0; u < 8; u++) CPA16(kdst + u * 16, ksrc + u * 16);
            const char* vsrc = vsrc0 + col1 * 2;
            const uint32_t vdst = ob + (vha ? BVL : BVH) + vrow * 144;
#pragma unroll
            for (int u = 0; u < 8; u++) CPA16(vdst + u * 16, vsrc + u * 16);
            CPA_COMMIT();
        }

        float sacc[8][4];
#pragma unroll
        for (int n = 0; n < 8; n++)
#pragma unroll
            for (int r = 0; r < 4; r++) sacc[n][r] = 0.0f;

        // ---- S = Q @ K^T : pass-major per ks ----
#pragma unroll
        for (int ks = 0; ks < 8; ks++) {
            uint32_t kh[4][4], kl[4][4];
#pragma unroll
            for (int n2 = 0; n2 < 4; n2++) {
                const uint32_t ka = sbuf + BKH +
                    (n2 * 16 + (lane & 7) + ((lane >> 4) & 1) * 8) * 272 +
                    ks * 32 + ((lane >> 3) & 1) * 16;
                ldsm4(kh[n2], ka);
                ldsm4(kl[n2], ka + 17408);
            }
#pragma unroll
            for (int n2 = 0; n2 < 4; n2++)
#pragma unroll
                for (int bb = 0; bb < 2; bb++)
                    mma16816(sacc[2 * n2 + bb], qfh[ks], &kh[n2][bb * 2]);
#pragma unroll
            for (int n2 = 0; n2 < 4; n2++)
#pragma unroll
                for (int bb = 0; bb < 2; bb++)
                    mma16816(sacc[2 * n2 + bb], qfl[ks], &kh[n2][bb * 2]);
#pragma unroll
            for (int n2 = 0; n2 < 4; n2++)
#pragma unroll
                for (int bb = 0; bb < 2; bb++)
                    mma16816(sacc[2 * n2 + bb], qfh[ks], &kl[n2][bb * 2]);
        }

        if (j >= 2 * qt) {
            const int rowlo = r0 + wid * 16 + g;
            const int colb  = j * 64 + qq * 2;
#pragma unroll
            for (int n = 0; n < 8; n++) {
                const int c0 = colb + n * 8, c1 = c0 + 1;
                if (c0 > rowlo)     sacc[n][0] = -1e30f;
                if (c1 > rowlo)     sacc[n][1] = -1e30f;
                if (c0 > rowlo + 8) sacc[n][2] = -1e30f;
                if (c1 > rowlo + 8) sacc[n][3] = -1e30f;
            }
        }

        float rm0 = -3e38f, rm1 = -3e38f;
#pragma unroll
        for (int n = 0; n < 8; n++) {
            rm0 = fmaxf(rm0, fmaxf(sacc[n][0], sacc[n][1]));
            rm1 = fmaxf(rm1, fmaxf(sacc[n][2], sacc[n][3]));
        }
        rm0 = fmaxf(rm0, __shfl_xor_sync(0xffffffffu, rm0, 1));
        rm0 = fmaxf(rm0, __shfl_xor_sync(0xffffffffu, rm0, 2));
        rm1 = fmaxf(rm1, __shfl_xor_sync(0xffffffffu, rm1, 1));
        rm1 = fmaxf(rm1, __shfl_xor_sync(0xffffffffu, rm1, 2));
        const float mn0 = fmaxf(m0, rm0), mn1 = fmaxf(m1, rm1);
        const float al0 = __expf(m0 - mn0), al1 = __expf(m1 - mn1);
        m0 = mn0; m1 = mn1;

        float rs0 = 0.0f, rs1 = 0.0f;
#pragma unroll
        for (int n = 0; n < 8; n++) {
            sacc[n][0] = __expf(sacc[n][0] - mn0);
            sacc[n][1] = __expf(sacc[n][1] - mn0);
            sacc[n][2] = __expf(sacc[n][2] - mn1);
            sacc[n][3] = __expf(sacc[n][3] - mn1);
            rs0 += sacc[n][0] + sacc[n][1];
            rs1 += sacc[n][2] + sacc[n][3];
        }
        rs0 += __shfl_xor_sync(0xffffffffu, rs0, 1);
        rs0 += __shfl_xor_sync(0xffffffffu, rs0, 2);
        rs1 += __shfl_xor_sync(0xffffffffu, rs1, 1);
        rs1 += __shfl_xor_sync(0xffffffffu, rs1, 2);
        l0 = l0 * al0 + rs0;
        l1 = l1 * al1 + rs1;

#pragma unroll
        for (int n = 0; n < 16; n++) {
            zacc[n][0] *= al0; zacc[n][1] *= al0;
            zacc[n][2] *= al1; zacc[n][3] *= al1;
        }

        uint32_t pa_h[4][4], pa_l[4][4];
#pragma unroll
        for (int kt = 0; kt < 4; kt++) {
            pa_h[kt][0] = pack_split(sacc[2*kt][0],   sacc[2*kt][1],   pa_l[kt][0]);
            pa_h[kt][1] = pack_split(sacc[2*kt][2],   sacc[2*kt][3],   pa_l[kt][1]);
            pa_h[kt][2] = pack_split(sacc[2*kt+1][0], sacc[2*kt+1][1], pa_l[kt][2]);
            pa_h[kt][3] = pack_split(sacc[2*kt+1][2], sacc[2*kt+1][3], pa_l[kt][3]);
        }

        // ---- Z += P @ V : pass-major per (kt, n-half) ----
#pragma unroll
        for (int kt = 0; kt < 4; kt++) {
#pragma unroll
            for (int h2 = 0; h2 < 2; h2++) {
                uint32_t vh[4][4], vl[4][4];
#pragma unroll
                for (int q4 = 0; q4 < 4; q4++) {
                    const int n2 = h2 * 4 + q4;
                    const uint32_t va = sbuf + BVH +
                        (n2 * 16 + (lane & 7) + ((lane >> 4) & 1) * 8) * 144 +
                        kt * 32 + ((lane >> 3) & 1) * 16;
                    ldsm4(vh[q4], va);
                    ldsm4(vl[q4], va + 18432);
                }
#pragma unroll
                for (int q4 = 0; q4 < 4; q4++)
#pragma unroll
                    for (int bb = 0; bb < 2; bb++)
                        mma16816(zacc[2 * (h2 * 4 + q4) + bb], pa_h[kt], &vh[q4][bb * 2]);
#pragma unroll
                for (int q4 = 0; q4 < 4; q4++)
#pragma unroll
                    for (int bb = 0; bb < 2; bb++)
                        mma16816(zacc[2 * (h2 * 4 + q4) + bb], pa_l[kt], &vh[q4][bb * 2]);
#pragma unroll
                for (int q4 = 0; q4 < 4; q4++)
#pragma unroll
                    for (int bb = 0; bb < 2; bb++)
                        mma16816(zacc[2 * (h2 * 4 + q4) + bb], pa_h[kt], &vl[q4][bb * 2]);
            }
        }
        __syncthreads();
    }

    const float i0 = 1.0f / l0, i1 = 1.0f / l1;
    float* zp = (float*)(g_heap + ZOFF);
    const int rowlo = r0 + wid * 16 + g;
#pragma unroll
    for (int n = 0; n < 16; n++) {
        const int col = h * 128 + n * 8 + qq * 2;
        *(float2*)(zp + (size_t)rowlo * 2048 + col) =
            make_float2(zacc[n][0] * i0, zacc[n][1] * i0);
        *(float2*)(zp + (size_t)(rowlo + 8) * 2048 + col) =
            make_float2(zacc[n][2] * i1, zacc[n][3] * i1);
    }
}

// ---------------------------------------------------------------------------
extern "C" void kernel_launch(void* const* d_in, const int* in_sizes, int n_in,
                              void* d_out, int out_size)
{
    const float* x     = (const float*)d_in[0];
    const float* q     = (const float*)d_in[1];
    const float* k     = (const float*)d_in[2];
    const float* v     = (const float*)d_in[3];
    const float* o     = (const float*)d_in[4];
    const float* theta = (const float*)d_in[5];
    float* out = (float*)d_out;

    cudaFuncSetAttribute(attn_hmma,
                         cudaFuncAttributeMaxDynamicSharedMemorySize, 212992);

    splitwT<<<dim3(64, 4, 16), dim3(32, 8)>>>(q);
    proj_v9<<<dim3(32, 16), 512>>>(x, QOFF);
    splitwT<<<dim3(64, 4, 16), dim3(32, 8)>>>(k);
    proj_v9<<<dim3(32, 16), 512>>>(x, KOFF);
    splitwT<<<dim3(64, 4, 16), dim3(32, 8)>>>(v);
    proj_v9<<<dim3(32, 16), 512>>>(x, ZOFF);
    rope_pack<<<dim3(1024, 16, 2), 256>>>(theta);
    tspv<<<dim3(128, 4, 16), dim3(32, 8)>>>();
    attn_hmma<<<512, 256, 212992>>>();
    osplitT<<<dim3(64, 64), dim3(32, 8)>>>(o);
    outproj_v9<<<dim3(32, 16), 512>>>(out);
}